// round 1
// baseline (speedup 1.0000x reference)
#include <cuda_runtime.h>
#include <stdint.h>

// HashGridEncoder: instant-NGP style multiresolution hash grid encode.
// x: [N,3] f32 in [0,1); aabb: [3] f32 (=1); table: [16, 2^19, 2] f32.
// out: [N, 32] f32.  Levels 0..2 are dense (res 16/32/64), 3..15 hashed.

#define HG_NUM_LEVELS 16
#define HG_TABLE_SIZE (1u << 19)
#define HG_MASK (HG_TABLE_SIZE - 1u)
#define HG_PRIME_Y 2654435761u
#define HG_PRIME_Z 805459861u

__global__ __launch_bounds__(256) void hashgrid_encode_kernel(
    const float* __restrict__ x,
    const float* __restrict__ aabb,
    const float* __restrict__ table,
    float* __restrict__ out,
    int n)
{
    // per-warp transpose tile: 32 points x 32 feats, padded to kill bank conflicts
    __shared__ float sbuf[8][32][33];

    const int tid  = blockIdx.x * blockDim.x + threadIdx.x;
    const int warp = threadIdx.x >> 5;
    const int lane = threadIdx.x & 31;
    const bool active = (tid < n);
    // clamp inactive lanes to a valid point so all gathers stay in-bounds
    // (results discarded at the guarded store)
    const int pi = active ? tid : 0;

    const float a0 = __ldg(aabb + 0);
    const float a1 = __ldg(aabb + 1);
    const float a2 = __ldg(aabb + 2);

    const float px_in = __ldg(x + 3 * (size_t)pi + 0);
    const float py_in = __ldg(x + 3 * (size_t)pi + 1);
    const float pz_in = __ldg(x + 3 * (size_t)pi + 2);

    // normalize_aabb then bound (-1,1) -> [0,1]; matches reference fp32 order
    const float xn0 = (px_in / a0 + 1.0f) * 0.5f;
    const float xn1 = (py_in / a1 + 1.0f) * 0.5f;
    const float xn2 = (pz_in / a2 + 1.0f) * 0.5f;

    const float2* __restrict__ tab = (const float2*)table;

#pragma unroll
    for (int l = 0; l < HG_NUM_LEVELS; ++l) {
        const unsigned res = 16u << l;           // floor(16 * 2^l), exact
        const float resf = (float)res;

        const float px = xn0 * resf;
        const float py = xn1 * resf;
        const float pz = xn2 * resf;
        const float fx = floorf(px);
        const float fy = floorf(py);
        const float fz = floorf(pz);
        const float tx = px - fx;
        const float ty = py - fy;
        const float tz = pz - fz;
        const unsigned cx = (unsigned)fx;
        const unsigned cy = (unsigned)fy;
        const unsigned cz = (unsigned)fz;

        unsigned i000, i100, i010, i110, i001, i101, i011, i111;
        // dense iff (res+1)^3 <= TABLE_SIZE  (levels 0..2). Constant-folded.
        if ((unsigned long long)(res + 1) * (res + 1) * (res + 1) <=
            (unsigned long long)HG_TABLE_SIZE) {
            const unsigned s  = res + 1;
            const unsigned s2 = s * s;
            const unsigned base = cx + cy * s + cz * s2;
            i000 = base;          i100 = base + 1;
            i010 = base + s;      i110 = base + s + 1;
            i001 = base + s2;     i101 = base + s2 + 1;
            i011 = base + s + s2; i111 = base + s + s2 + 1;
        } else {
            const unsigned hy0 = cy * HG_PRIME_Y, hy1 = hy0 + HG_PRIME_Y;
            const unsigned hz0 = cz * HG_PRIME_Z, hz1 = hz0 + HG_PRIME_Z;
            const unsigned e00 = hy0 ^ hz0, e10 = hy1 ^ hz0;
            const unsigned e01 = hy0 ^ hz1, e11 = hy1 ^ hz1;
            const unsigned cx1 = cx + 1u;
            i000 = (cx  ^ e00) & HG_MASK;  i100 = (cx1 ^ e00) & HG_MASK;
            i010 = (cx  ^ e10) & HG_MASK;  i110 = (cx1 ^ e10) & HG_MASK;
            i001 = (cx  ^ e01) & HG_MASK;  i101 = (cx1 ^ e01) & HG_MASK;
            i011 = (cx  ^ e11) & HG_MASK;  i111 = (cx1 ^ e11) & HG_MASK;
        }

        const float2* __restrict__ tl = tab + (size_t)l * HG_TABLE_SIZE;
        // 8 independent gathers -> MLP=8 within the level
        const float2 v000 = __ldg(tl + i000);
        const float2 v100 = __ldg(tl + i100);
        const float2 v010 = __ldg(tl + i010);
        const float2 v110 = __ldg(tl + i110);
        const float2 v001 = __ldg(tl + i001);
        const float2 v101 = __ldg(tl + i101);
        const float2 v011 = __ldg(tl + i011);
        const float2 v111 = __ldg(tl + i111);

        const float wx1 = tx, wx0 = 1.0f - tx;
        const float wy1 = ty, wy0 = 1.0f - ty;
        const float wz1 = tz, wz0 = 1.0f - tz;
        const float w00 = wy0 * wz0, w10 = wy1 * wz0;
        const float w01 = wy0 * wz1, w11 = wy1 * wz1;
        const float w000 = wx0 * w00, w100 = wx1 * w00;
        const float w010 = wx0 * w10, w110 = wx1 * w10;
        const float w001 = wx0 * w01, w101 = wx1 * w01;
        const float w011 = wx0 * w11, w111 = wx1 * w11;

        const float f0 = w000 * v000.x + w100 * v100.x + w010 * v010.x +
                         w110 * v110.x + w001 * v001.x + w101 * v101.x +
                         w011 * v011.x + w111 * v111.x;
        const float f1 = w000 * v000.y + w100 * v100.y + w010 * v010.y +
                         w110 * v110.y + w001 * v001.y + w101 * v101.y +
                         w011 * v011.y + w111 * v111.y;

        sbuf[warp][lane][2 * l]     = f0;
        sbuf[warp][lane][2 * l + 1] = f1;
    }

    __syncwarp();

    // coalesced transposed store: each warp writes 32 contiguous 128B rows
    const int base_pt = blockIdx.x * blockDim.x + warp * 32;
#pragma unroll
    for (int r = 0; r < 32; ++r) {
        const int pt = base_pt + r;
        if (pt < n) {
            out[(size_t)pt * 32 + lane] = sbuf[warp][r][lane];
        }
    }
}

extern "C" void kernel_launch(void* const* d_in, const int* in_sizes, int n_in,
                              void* d_out, int out_size) {
    const float* x     = (const float*)d_in[0];   // [N,3]
    const float* aabb  = (const float*)d_in[1];   // [3]
    const float* table = (const float*)d_in[2];   // [16, 2^19, 2]
    float* out = (float*)d_out;                   // [N, 32]

    const int n = in_sizes[0] / 3;
    const int threads = 256;
    const int blocks = (n + threads - 1) / threads;
    hashgrid_encode_kernel<<<blocks, threads>>>(x, aabb, table, out, n);
}

// round 2
// speedup vs baseline: 1.0217x; 1.0217x over previous
#include <cuda_runtime.h>
#include <stdint.h>

// HashGridEncoder: instant-NGP multiresolution hash grid encode.
// x: [N,3] f32; aabb: [3] f32; table: [16, 2^19, 2] f32. out: [N,32] f32.
// Levels 0..2 dense (res 16/32/64), 3..15 hashed.
// R2: two levels' gathers in flight per warp (MLP=16) to cover L2-hit latency.

#define HG_NUM_LEVELS 16
#define HG_TABLE_SIZE (1u << 19)
#define HG_MASK (HG_TABLE_SIZE - 1u)
#define HG_PRIME_Y 2654435761u
#define HG_PRIME_Z 805459861u

struct LevelSetup {
    unsigned idx[8];
    float tx, ty, tz;
};

// l is a compile-time constant in the unrolled caller; dense/hashed branch folds.
__device__ __forceinline__ void level_setup(
    int l, float xn0, float xn1, float xn2, LevelSetup& s)
{
    const unsigned res = 16u << l;
    const float resf = (float)res;

    const float px = xn0 * resf;
    const float py = xn1 * resf;
    const float pz = xn2 * resf;
    const float fx = floorf(px);
    const float fy = floorf(py);
    const float fz = floorf(pz);
    s.tx = px - fx;
    s.ty = py - fy;
    s.tz = pz - fz;
    const unsigned cx = (unsigned)fx;
    const unsigned cy = (unsigned)fy;
    const unsigned cz = (unsigned)fz;

    if ((unsigned long long)(res + 1) * (res + 1) * (res + 1) <=
        (unsigned long long)HG_TABLE_SIZE) {
        const unsigned st = res + 1;
        const unsigned s2 = st * st;
        const unsigned base = cx + cy * st + cz * s2;
        s.idx[0] = base;           s.idx[1] = base + 1;
        s.idx[2] = base + st;      s.idx[3] = base + st + 1;
        s.idx[4] = base + s2;      s.idx[5] = base + s2 + 1;
        s.idx[6] = base + st + s2; s.idx[7] = base + st + s2 + 1;
    } else {
        const unsigned hy0 = cy * HG_PRIME_Y, hy1 = hy0 + HG_PRIME_Y;
        const unsigned hz0 = cz * HG_PRIME_Z, hz1 = hz0 + HG_PRIME_Z;
        const unsigned e00 = hy0 ^ hz0, e10 = hy1 ^ hz0;
        const unsigned e01 = hy0 ^ hz1, e11 = hy1 ^ hz1;
        const unsigned cx1 = cx + 1u;
        s.idx[0] = (cx  ^ e00) & HG_MASK;  s.idx[1] = (cx1 ^ e00) & HG_MASK;
        s.idx[2] = (cx  ^ e10) & HG_MASK;  s.idx[3] = (cx1 ^ e10) & HG_MASK;
        s.idx[4] = (cx  ^ e01) & HG_MASK;  s.idx[5] = (cx1 ^ e01) & HG_MASK;
        s.idx[6] = (cx  ^ e11) & HG_MASK;  s.idx[7] = (cx1 ^ e11) & HG_MASK;
    }
}

__device__ __forceinline__ void level_reduce(
    const LevelSetup& s, const float2 v[8], float& f0, float& f1)
{
    const float wx1 = s.tx, wx0 = 1.0f - s.tx;
    const float wy1 = s.ty, wy0 = 1.0f - s.ty;
    const float wz1 = s.tz, wz0 = 1.0f - s.tz;
    const float w00 = wy0 * wz0, w10 = wy1 * wz0;
    const float w01 = wy0 * wz1, w11 = wy1 * wz1;
    const float w000 = wx0 * w00, w100 = wx1 * w00;
    const float w010 = wx0 * w10, w110 = wx1 * w10;
    const float w001 = wx0 * w01, w101 = wx1 * w01;
    const float w011 = wx0 * w11, w111 = wx1 * w11;

    f0 = w000 * v[0].x + w100 * v[1].x + w010 * v[2].x + w110 * v[3].x +
         w001 * v[4].x + w101 * v[5].x + w011 * v[6].x + w111 * v[7].x;
    f1 = w000 * v[0].y + w100 * v[1].y + w010 * v[2].y + w110 * v[3].y +
         w001 * v[4].y + w101 * v[5].y + w011 * v[6].y + w111 * v[7].y;
}

__global__ __launch_bounds__(128) void hashgrid_encode_kernel(
    const float* __restrict__ x,
    const float* __restrict__ aabb,
    const float* __restrict__ table,
    float* __restrict__ out,
    int n)
{
    // per-warp transpose tile: 32 points x 32 feats, padded (33) -> conflict-free
    __shared__ float sbuf[4][32][33];

    const int tid  = blockIdx.x * blockDim.x + threadIdx.x;
    const int warp = threadIdx.x >> 5;
    const int lane = threadIdx.x & 31;
    const bool active = (tid < n);
    const int pi = active ? tid : 0;   // clamp so gathers stay in-bounds

    const float a0 = __ldg(aabb + 0);
    const float a1 = __ldg(aabb + 1);
    const float a2 = __ldg(aabb + 2);

    const float px_in = __ldg(x + 3 * (size_t)pi + 0);
    const float py_in = __ldg(x + 3 * (size_t)pi + 1);
    const float pz_in = __ldg(x + 3 * (size_t)pi + 2);

    // normalize_aabb then bound (-1,1) -> [0,1]; matches reference fp32 order
    const float xn0 = (px_in / a0 + 1.0f) * 0.5f;
    const float xn1 = (py_in / a1 + 1.0f) * 0.5f;
    const float xn2 = (pz_in / a2 + 1.0f) * 0.5f;

    const float2* __restrict__ tab = (const float2*)table;

#pragma unroll
    for (int lp = 0; lp < HG_NUM_LEVELS / 2; ++lp) {
        const int la = 2 * lp;
        const int lb = 2 * lp + 1;

        LevelSetup sa, sb;
        level_setup(la, xn0, xn1, xn2, sa);
        level_setup(lb, xn0, xn1, xn2, sb);

        const float2* __restrict__ tla = tab + (size_t)la * HG_TABLE_SIZE;
        const float2* __restrict__ tlb = tab + (size_t)lb * HG_TABLE_SIZE;

        // issue all 16 gathers before consuming any -> MLP=16
        float2 va[8], vb[8];
#pragma unroll
        for (int j = 0; j < 8; ++j) va[j] = __ldg(tla + sa.idx[j]);
#pragma unroll
        for (int j = 0; j < 8; ++j) vb[j] = __ldg(tlb + sb.idx[j]);

        float fa0, fa1, fb0, fb1;
        level_reduce(sa, va, fa0, fa1);
        level_reduce(sb, vb, fb0, fb1);

        sbuf[warp][lane][2 * la]     = fa0;
        sbuf[warp][lane][2 * la + 1] = fa1;
        sbuf[warp][lane][2 * lb]     = fb0;
        sbuf[warp][lane][2 * lb + 1] = fb1;
    }

    __syncwarp();

    // coalesced transposed store: each warp writes 32 contiguous 128B rows
    const int base_pt = blockIdx.x * blockDim.x + warp * 32;
#pragma unroll
    for (int r = 0; r < 32; ++r) {
        const int pt = base_pt + r;
        if (pt < n) {
            out[(size_t)pt * 32 + lane] = sbuf[warp][r][lane];
        }
    }
}

extern "C" void kernel_launch(void* const* d_in, const int* in_sizes, int n_in,
                              void* d_out, int out_size) {
    const float* x     = (const float*)d_in[0];   // [N,3]
    const float* aabb  = (const float*)d_in[1];   // [3]
    const float* table = (const float*)d_in[2];   // [16, 2^19, 2]
    float* out = (float*)d_out;                   // [N, 32]

    const int n = in_sizes[0] / 3;
    const int threads = 128;
    const int blocks = (n + threads - 1) / threads;
    hashgrid_encode_kernel<<<blocks, threads>>>(x, aabb, table, out, n);
}

// round 3
// speedup vs baseline: 2.0939x; 2.0494x over previous
#include <cuda_runtime.h>
#include <stdint.h>

// HashGridEncoder: instant-NGP multiresolution hash grid encode.
// x: [N,3] f32; aabb: [3] f32; table: [16, 2^19, 2] f32. out: [N,32] f32.
// Levels 0..2 dense (res 16/32/64), 3..15 hashed.
// R3: half-size transpose tile (two store phases) so smem stops capping
// occupancy (52 -> 64 warps/SM at regs=32).

#define HG_NUM_LEVELS 16
#define HG_TABLE_SIZE (1u << 19)
#define HG_MASK (HG_TABLE_SIZE - 1u)
#define HG_PRIME_Y 2654435761u
#define HG_PRIME_Z 805459861u

struct LevelSetup {
    unsigned idx[8];
    float tx, ty, tz;
};

// l is compile-time constant in the unrolled caller; dense/hashed branch folds.
__device__ __forceinline__ void level_setup(
    int l, float xn0, float xn1, float xn2, LevelSetup& s)
{
    const unsigned res = 16u << l;
    const float resf = (float)res;

    const float px = xn0 * resf;
    const float py = xn1 * resf;
    const float pz = xn2 * resf;
    const float fx = floorf(px);
    const float fy = floorf(py);
    const float fz = floorf(pz);
    s.tx = px - fx;
    s.ty = py - fy;
    s.tz = pz - fz;
    const unsigned cx = (unsigned)fx;
    const unsigned cy = (unsigned)fy;
    const unsigned cz = (unsigned)fz;

    if ((unsigned long long)(res + 1) * (res + 1) * (res + 1) <=
        (unsigned long long)HG_TABLE_SIZE) {
        const unsigned st = res + 1;
        const unsigned s2 = st * st;
        const unsigned base = cx + cy * st + cz * s2;
        s.idx[0] = base;           s.idx[1] = base + 1;
        s.idx[2] = base + st;      s.idx[3] = base + st + 1;
        s.idx[4] = base + s2;      s.idx[5] = base + s2 + 1;
        s.idx[6] = base + st + s2; s.idx[7] = base + st + s2 + 1;
    } else {
        const unsigned hy0 = cy * HG_PRIME_Y, hy1 = hy0 + HG_PRIME_Y;
        const unsigned hz0 = cz * HG_PRIME_Z, hz1 = hz0 + HG_PRIME_Z;
        const unsigned e00 = hy0 ^ hz0, e10 = hy1 ^ hz0;
        const unsigned e01 = hy0 ^ hz1, e11 = hy1 ^ hz1;
        const unsigned cx1 = cx + 1u;
        s.idx[0] = (cx  ^ e00) & HG_MASK;  s.idx[1] = (cx1 ^ e00) & HG_MASK;
        s.idx[2] = (cx  ^ e10) & HG_MASK;  s.idx[3] = (cx1 ^ e10) & HG_MASK;
        s.idx[4] = (cx  ^ e01) & HG_MASK;  s.idx[5] = (cx1 ^ e01) & HG_MASK;
        s.idx[6] = (cx  ^ e11) & HG_MASK;  s.idx[7] = (cx1 ^ e11) & HG_MASK;
    }
}

__device__ __forceinline__ void level_reduce(
    const LevelSetup& s, const float2 v[8], float& f0, float& f1)
{
    const float wx1 = s.tx, wx0 = 1.0f - s.tx;
    const float wy1 = s.ty, wy0 = 1.0f - s.ty;
    const float wz1 = s.tz, wz0 = 1.0f - s.tz;
    const float w00 = wy0 * wz0, w10 = wy1 * wz0;
    const float w01 = wy0 * wz1, w11 = wy1 * wz1;
    const float w000 = wx0 * w00, w100 = wx1 * w00;
    const float w010 = wx0 * w10, w110 = wx1 * w10;
    const float w001 = wx0 * w01, w101 = wx1 * w01;
    const float w011 = wx0 * w11, w111 = wx1 * w11;

    f0 = w000 * v[0].x + w100 * v[1].x + w010 * v[2].x + w110 * v[3].x +
         w001 * v[4].x + w101 * v[5].x + w011 * v[6].x + w111 * v[7].x;
    f1 = w000 * v[0].y + w100 * v[1].y + w010 * v[2].y + w110 * v[3].y +
         w001 * v[4].y + w101 * v[5].y + w011 * v[6].y + w111 * v[7].y;
}

__global__ __launch_bounds__(128) void hashgrid_encode_kernel(
    const float* __restrict__ x,
    const float* __restrict__ aabb,
    const float* __restrict__ table,
    float* __restrict__ out,
    int n)
{
    // per-warp HALF tile: 32 points x 16 feats (levels 0-7, reused for 8-15)
    // padded to 17 to keep the transposed read conflict-free
    __shared__ float sbuf[4][32][17];

    const int tid  = blockIdx.x * blockDim.x + threadIdx.x;
    const int warp = threadIdx.x >> 5;
    const int lane = threadIdx.x & 31;
    const bool active = (tid < n);
    const int pi = active ? tid : 0;   // clamp so gathers stay in-bounds

    const float a0 = __ldg(aabb + 0);
    const float a1 = __ldg(aabb + 1);
    const float a2 = __ldg(aabb + 2);

    const float px_in = __ldg(x + 3 * (size_t)pi + 0);
    const float py_in = __ldg(x + 3 * (size_t)pi + 1);
    const float pz_in = __ldg(x + 3 * (size_t)pi + 2);

    // normalize_aabb then bound (-1,1) -> [0,1]; matches reference fp32 order
    const float xn0 = (px_in / a0 + 1.0f) * 0.5f;
    const float xn1 = (py_in / a1 + 1.0f) * 0.5f;
    const float xn2 = (pz_in / a2 + 1.0f) * 0.5f;

    const float2* __restrict__ tab = (const float2*)table;
    const int base_pt = blockIdx.x * blockDim.x + warp * 32;

#pragma unroll
    for (int half = 0; half < 2; ++half) {
#pragma unroll
        for (int lp = 0; lp < 4; ++lp) {
            const int la = half * 8 + 2 * lp;
            const int lb = la + 1;

            LevelSetup sa, sb;
            level_setup(la, xn0, xn1, xn2, sa);
            level_setup(lb, xn0, xn1, xn2, sb);

            const float2* __restrict__ tla = tab + (size_t)la * HG_TABLE_SIZE;
            const float2* __restrict__ tlb = tab + (size_t)lb * HG_TABLE_SIZE;

            float2 va[8], vb[8];
#pragma unroll
            for (int j = 0; j < 8; ++j) va[j] = __ldg(tla + sa.idx[j]);
#pragma unroll
            for (int j = 0; j < 8; ++j) vb[j] = __ldg(tlb + sb.idx[j]);

            float fa0, fa1, fb0, fb1;
            level_reduce(sa, va, fa0, fa1);
            level_reduce(sb, vb, fb0, fb1);

            const int c = 2 * (2 * lp);          // 0,4,8,12 within the half-tile
            sbuf[warp][lane][c + 0] = fa0;
            sbuf[warp][lane][c + 1] = fa1;
            sbuf[warp][lane][c + 2] = fb0;
            sbuf[warp][lane][c + 3] = fb1;
        }

        __syncwarp();

        // coalesced transposed store of this half: 32 rows x 16 floats (64B)
#pragma unroll
        for (int rr = 0; rr < 16; ++rr) {
            const int r = 2 * rr + (lane >> 4);      // two rows per iteration
            const int c = lane & 15;
            const int pt = base_pt + r;
            if (pt < n) {
                out[(size_t)pt * 32 + half * 16 + c] = sbuf[warp][r][c];
            }
        }

        __syncwarp();   // tile reuse hazard between halves
    }
}

extern "C" void kernel_launch(void* const* d_in, const int* in_sizes, int n_in,
                              void* d_out, int out_size) {
    const float* x     = (const float*)d_in[0];   // [N,3]
    const float* aabb  = (const float*)d_in[1];   // [3]
    const float* table = (const float*)d_in[2];   // [16, 2^19, 2]
    float* out = (float*)d_out;                   // [N, 32]

    const int n = in_sizes[0] / 3;
    const int threads = 128;
    const int blocks = (n + threads - 1) / threads;
    hashgrid_encode_kernel<<<blocks, threads>>>(x, aabb, table, out, n);
}